// round 14
// baseline (speedup 1.0000x reference)
#include <cuda_runtime.h>
#include <cstdint>

#define KV 16
#define DIM 15
#define NPIX (2048 * 2048)
#define TPB 256
#define STAGES 4
#define NBLK 2048   // NBLK * TPB * STAGES == NPIX/2 pixel-pairs exactly
#define SMEM_BYTES (2 * DIM * TPB * 8)   // 61,440 B: double-buffered [2][DIM][TPB] u64

typedef unsigned long long u64;

__device__ __forceinline__ u64 ffma2(u64 a, u64 b, u64 c) {
    u64 d;
    asm("fma.rn.f32x2 %0, %1, %2, %3;" : "=l"(d) : "l"(a), "l"(b), "l"(c));
    return d;
}
__device__ __forceinline__ u64 fadd2(u64 a, u64 b) {
    u64 d;
    asm("add.rn.f32x2 %0, %1, %2;" : "=l"(d) : "l"(a), "l"(b));
    return d;
}
__device__ __forceinline__ u64 pack2(float x, float y) {
    u64 p;
    asm("mov.b64 %0, {%1, %2};" : "=l"(p) : "f"(x), "f"(y));
    return p;
}
__device__ __forceinline__ void unpack2(u64 p, float& x, float& y) {
    asm("mov.b64 {%0, %1}, %2;" : "=f"(x), "=f"(y) : "l"(p));
}
__device__ __forceinline__ void cp_async8(uint32_t dst, const void* src) {
    asm volatile("cp.async.ca.shared.global [%0], [%1], 8;"
                 :: "r"(dst), "l"(src) : "memory");
}
__device__ __forceinline__ void cp_commit() {
    asm volatile("cp.async.commit_group;" ::: "memory");
}
__device__ __forceinline__ void cp_wait1() {
    asm volatile("cp.async.wait_group 1;" ::: "memory");
}
__device__ __forceinline__ void cp_wait0() {
    asm volatile("cp.async.wait_group 0;" ::: "memory");
}

// Embed vertex index k into the low 4 mantissa bits of t (one LOP3), so the
// argmin collapses to a chain of FMNMX. Perturbation <= 16 ulp.
__device__ __forceinline__ float embed_idx(float t, int k) {
    unsigned r;
    asm("lop3.b32 %0, %1, 0xFFFFFFF0, %2, 0xEA;"  // (a & b) | c
        : "=r"(r) : "r"(__float_as_uint(t)), "r"(k));
    return __uint_as_float(r);
}

// Weight layout, per vertex k: 8 ulonglong2.
//   [k][m].x / .y = packed (-2*v[k][2m], dup) / (-2*v[k][2m+1], dup)  for m<7
//   [k][7].x      = packed pair for j=14
//   [k][7].y      = packed (||v_k||^2, ||v_k||^2)
__constant__ ulonglong2 c_wp[KV][8];

// prep writes through the global alias of c_wp; const cache refills per launch.
__global__ void prep_kernel(const float* __restrict__ v, ulonglong2* __restrict__ wp) {
    const int t = threadIdx.x;
    if (t < KV) {
        float b = 0.0f;
        #pragma unroll
        for (int j = 0; j < DIM; ++j) {
            float a = v[t * DIM + j];
            b = fmaf(a, a, b);
        }
        #pragma unroll
        for (int m = 0; m < 7; ++m) {
            float w0 = -2.0f * v[t * DIM + 2 * m];
            float w1 = -2.0f * v[t * DIM + 2 * m + 1];
            wp[t * 8 + m] = make_ulonglong2(pack2(w0, w0), pack2(w1, w1));
        }
        float w14 = -2.0f * v[t * DIM + 14];
        wp[t * 8 + 7] = make_ulonglong2(pack2(w14, w14), pack2(b, b));
    }
}

// t_k = ||v_k||^2 - 2 v_k . z   (monotone in distance; argmin matches)
// dmin = sqrt(max(zz + t_min, 0))
//
// Pipeline: per stage, each thread cp.asyncs its OWN 15 x 8B (plane-major)
// into smem (register-free prefetch), computes the previous stage from
// registers. Thread-private smem slots => no __syncthreads needed.

extern __shared__ u64 sbuf[];   // [2][DIM][TPB]

__global__ __launch_bounds__(TPB, 2) void gum_kernel(const float* __restrict__ z,
                                                     float* __restrict__ out) {
    const int t = threadIdx.x;
    const size_t base = (size_t)blockIdx.x * (TPB * STAGES) + t;  // pair index
    const u64* zp = (const u64*)z;
    const uint32_t sb = (uint32_t)__cvta_generic_to_shared(sbuf);

    // Prologue: stage 0 -> buffer 0
    #pragma unroll
    for (int j = 0; j < DIM; ++j)
        cp_async8(sb + (uint32_t)((j * TPB + t) * 8),
                  zp + (size_t)j * (NPIX / 2) + base);
    cp_commit();

    #pragma unroll 1   // keep body (~9KB) inside L1.5 I$
    for (int s = 0; s < STAGES; ++s) {
        const size_t p = base + (size_t)s * TPB;

        if (s + 1 < STAGES) {
            const uint32_t nb = (uint32_t)((s + 1) & 1) * (DIM * TPB * 8);
            #pragma unroll
            for (int j = 0; j < DIM; ++j)
                cp_async8(sb + nb + (uint32_t)((j * TPB + t) * 8),
                          zp + (size_t)j * (NPIX / 2) + p + TPB);
            cp_commit();
            cp_wait1();   // stage s complete; s+1 still in flight
        } else {
            cp_wait0();
        }

        const u64* buf = sbuf + (size_t)(s & 1) * (DIM * TPB);
        u64 zr[DIM];
        #pragma unroll
        for (int j = 0; j < DIM; ++j)
            zr[j] = buf[j * TPB + t];   // conflict-free LDS.64

        float b0 = __int_as_float(0x7f7fffff), b1 = b0;  // FLT_MAX

        #pragma unroll
        for (int k = 0; k < KV; ++k) {
            ulonglong2 w7 = c_wp[k][7];
            u64 la = w7.y;               // ||v_k||^2 pair
            #pragma unroll
            for (int m = 0; m < 7; ++m) {
                ulonglong2 w = c_wp[k][m];
                la = ffma2(w.x, zr[2 * m], la);
                la = ffma2(w.y, zr[2 * m + 1], la);
            }
            la = ffma2(w7.x, zr[14], la);

            float t0, t1;
            unpack2(la, t0, t1);
            b0 = fminf(b0, embed_idx(t0, k));
            b1 = fminf(b1, embed_idx(t1, k));
        }

        // ||z||^2 with two split chains
        u64 za = 0ull, zb = 0ull;
        #pragma unroll
        for (int j = 0; j < DIM; j += 2) {
            za = ffma2(zr[j], zr[j], za);
            if (j + 1 < DIM) zb = ffma2(zr[j + 1], zr[j + 1], zb);
        }
        float zz0, zz1;
        unpack2(fadd2(za, zb), zz0, zz1);

        unsigned u0 = __float_as_uint(b0), u1 = __float_as_uint(b1);
        float2 xo = make_float2((float)(u0 & 15u), (float)(u1 & 15u));
        float m0 = __uint_as_float(u0 & 0xFFFFFFF0u);
        float m1 = __uint_as_float(u1 & 0xFFFFFFF0u);
        float2 dm = make_float2(sqrtf(fmaxf(zz0 + m0, 0.0f)),
                                sqrtf(fmaxf(zz1 + m1, 0.0f)));

        __stcs((float2*)(out + 2 * p), xo);
        __stcs((float2*)(out + (size_t)NPIX + 2 * p), dm);
    }
}

extern "C" void kernel_launch(void* const* d_in, const int* in_sizes, int n_in,
                              void* d_out, int out_size) {
    const float* z = (const float*)d_in[0];  // (15, 2048, 2048) fp32
    const float* v = (const float*)d_in[1];  // (16, 15) fp32
    float* out = (float*)d_out;              // [X (as float) | dmin], each NPIX

    void* wp = nullptr;
    cudaGetSymbolAddress(&wp, c_wp);         // global alias of constant bank
    prep_kernel<<<1, 32>>>(v, (ulonglong2*)wp);

    cudaFuncSetAttribute(gum_kernel, cudaFuncAttributeMaxDynamicSharedMemorySize,
                         SMEM_BYTES);
    gum_kernel<<<NBLK, TPB, SMEM_BYTES>>>(z, out);
}

// round 15
// speedup vs baseline: 1.0807x; 1.0807x over previous
#include <cuda_runtime.h>
#include <cstdint>

#define KV 16
#define DIM 15
#define NPIX (2048 * 2048)
#define TPB 256
#define PAIRS 256                       // pixel-pairs per stage (== TPB)
#define STAGES 8
#define NBLK 1024                       // 1024*8*256 = NPIX/2 pairs exactly
#define PLANE_BYTES (PAIRS * 8)         // 2048 B per plane per stage (one bulk req)
#define STAGE_BYTES (DIM * PLANE_BYTES) // 30720
#define SMEM_BYTES (2 * STAGE_BYTES)    // 61440, double-buffered

typedef unsigned long long u64;

__device__ __forceinline__ u64 ffma2(u64 a, u64 b, u64 c) {
    u64 d;
    asm("fma.rn.f32x2 %0, %1, %2, %3;" : "=l"(d) : "l"(a), "l"(b), "l"(c));
    return d;
}
__device__ __forceinline__ u64 fadd2(u64 a, u64 b) {
    u64 d;
    asm("add.rn.f32x2 %0, %1, %2;" : "=l"(d) : "l"(a), "l"(b));
    return d;
}
__device__ __forceinline__ u64 pack2(float x, float y) {
    u64 p;
    asm("mov.b64 %0, {%1, %2};" : "=l"(p) : "f"(x), "f"(y));
    return p;
}
__device__ __forceinline__ void unpack2(u64 p, float& x, float& y) {
    asm("mov.b64 {%0, %1}, %2;" : "=f"(x), "=f"(y) : "l"(p));
}
__device__ __forceinline__ float embed_idx(float t, int k) {
    unsigned r;
    asm("lop3.b32 %0, %1, 0xFFFFFFF0, %2, 0xEA;"  // (a & b) | c
        : "=r"(r) : "r"(__float_as_uint(t)), "r"(k));
    return __uint_as_float(r);
}

// ---- bulk-copy / mbarrier primitives ----
__device__ __forceinline__ void mbar_init(uint32_t mbar, uint32_t count) {
    asm volatile("mbarrier.init.shared.b64 [%0], %1;" :: "r"(mbar), "r"(count) : "memory");
}
__device__ __forceinline__ void mbar_expect_tx(uint32_t mbar, uint32_t bytes) {
    asm volatile("mbarrier.arrive.expect_tx.shared.b64 _, [%0], %1;"
                 :: "r"(mbar), "r"(bytes) : "memory");
}
__device__ __forceinline__ void bulk_g2s(uint32_t dst, const void* src,
                                         uint32_t bytes, uint32_t mbar) {
    asm volatile("cp.async.bulk.shared::cta.global.mbarrier::complete_tx::bytes "
                 "[%0], [%1], %2, [%3];"
                 :: "r"(dst), "l"(src), "r"(bytes), "r"(mbar) : "memory");
}
__device__ __forceinline__ void mbar_wait(uint32_t mbar, uint32_t parity) {
    asm volatile(
        "{\n\t"
        ".reg .pred P;\n\t"
        "WL_%=:\n\t"
        "mbarrier.try_wait.parity.acquire.cta.shared::cta.b64 P, [%0], %1, 0x989680;\n\t"
        "@P bra.uni WD_%=;\n\t"
        "bra.uni WL_%=;\n\t"
        "WD_%=:\n\t"
        "}"
        :: "r"(mbar), "r"(parity) : "memory");
}

// Weight layout, per vertex k: 8 ulonglong2 in the constant bank.
//   [k][m].x / .y = packed (-2*v[k][2m], dup) / (-2*v[k][2m+1], dup)  for m<7
//   [k][7].x      = packed pair for j=14
//   [k][7].y      = packed (||v_k||^2, ||v_k||^2)
__constant__ ulonglong2 c_wp[KV][8];

// prep writes through the global alias of c_wp; const cache refills per launch.
__global__ void prep_kernel(const float* __restrict__ v, ulonglong2* __restrict__ wp) {
    const int t = threadIdx.x;
    if (t < KV) {
        float b = 0.0f;
        #pragma unroll
        for (int j = 0; j < DIM; ++j) {
            float a = v[t * DIM + j];
            b = fmaf(a, a, b);
        }
        #pragma unroll
        for (int m = 0; m < 7; ++m) {
            float w0 = -2.0f * v[t * DIM + 2 * m];
            float w1 = -2.0f * v[t * DIM + 2 * m + 1];
            wp[t * 8 + m] = make_ulonglong2(pack2(w0, w0), pack2(w1, w1));
        }
        float w14 = -2.0f * v[t * DIM + 14];
        wp[t * 8 + 7] = make_ulonglong2(pack2(w14, w14), pack2(b, b));
    }
}

// t_k = ||v_k||^2 - 2 v_k . z   (monotone in distance; argmin matches)
// dmin = sqrt(max(zz + t_min, 0))
//
// Bulk pipeline: per stage one thread issues 15 x 2KB cp.async.bulk (one whole
// plane-row per request -> DRAM sees large contiguous bursts instead of
// thousands of interleaved 128B lines). Double-buffered; compute overlaps the
// in-flight stage.

extern __shared__ u64 sbuf[];            // [2][DIM][PAIRS]
__shared__ __align__(8) uint64_t mbar_s[2];

__global__ __launch_bounds__(TPB) void gum_kernel(const float* __restrict__ z,
                                                  float* __restrict__ out) {
    const int t = threadIdx.x;
    const size_t cta_base = (size_t)blockIdx.x * (STAGES * PAIRS);  // pair idx
    const u64* zp = (const u64*)z;
    const uint32_t sb = (uint32_t)__cvta_generic_to_shared(sbuf);
    const uint32_t mb = (uint32_t)__cvta_generic_to_shared(mbar_s);

    if (t == 0) {
        mbar_init(mb, 1);
        mbar_init(mb + 8, 1);
    }
    __syncthreads();

    // Prologue: stage 0 -> buffer 0
    if (t == 0) {
        mbar_expect_tx(mb, STAGE_BYTES);
        #pragma unroll
        for (int j = 0; j < DIM; ++j)
            bulk_g2s(sb + (uint32_t)(j * PLANE_BYTES),
                     zp + (size_t)j * (NPIX / 2) + cta_base,
                     PLANE_BYTES, mb);
    }

    #pragma unroll 1
    for (int s = 0; s < STAGES; ++s) {
        const size_t p = cta_base + (size_t)s * PAIRS + t;
        const uint32_t buf = (uint32_t)(s & 1);
        const uint32_t par = (uint32_t)((s >> 1) & 1);

        mbar_wait(mb + buf * 8, par);

        // Register-load this thread's 15 pairs (conflict-free LDS.64)
        const u64* bptr = sbuf + (size_t)buf * (DIM * PAIRS);
        u64 zr[DIM];
        #pragma unroll
        for (int j = 0; j < DIM; ++j)
            zr[j] = bptr[j * PAIRS + t];

        // All threads have consumed buffer `buf` of stage s-? : after this
        // sync the OTHER buffer (used by stage s-1) is reusable for s+1.
        __syncthreads();

        if (s + 1 < STAGES && t == 0) {
            const uint32_t nbuf = (uint32_t)((s + 1) & 1);
            mbar_expect_tx(mb + nbuf * 8, STAGE_BYTES);
            #pragma unroll
            for (int j = 0; j < DIM; ++j)
                bulk_g2s(sb + nbuf * STAGE_BYTES + (uint32_t)(j * PLANE_BYTES),
                         zp + (size_t)j * (NPIX / 2) + p + (PAIRS - t),
                         PLANE_BYTES, mb + nbuf * 8);
        }

        // ---- compute (R12 dieted loop, PPT=2) ----
        float b0 = __int_as_float(0x7f7fffff), b1 = b0;  // FLT_MAX

        #pragma unroll
        for (int k = 0; k < KV; ++k) {
            ulonglong2 w7 = c_wp[k][7];
            u64 la = w7.y;               // ||v_k||^2 pair
            #pragma unroll
            for (int m = 0; m < 7; ++m) {
                ulonglong2 w = c_wp[k][m];
                la = ffma2(w.x, zr[2 * m], la);
                la = ffma2(w.y, zr[2 * m + 1], la);
            }
            la = ffma2(w7.x, zr[14], la);

            float t0, t1;
            unpack2(la, t0, t1);
            b0 = fminf(b0, embed_idx(t0, k));
            b1 = fminf(b1, embed_idx(t1, k));
        }

        u64 za = 0ull, zb = 0ull;
        #pragma unroll
        for (int j = 0; j < DIM; j += 2) {
            za = ffma2(zr[j], zr[j], za);
            if (j + 1 < DIM) zb = ffma2(zr[j + 1], zr[j + 1], zb);
        }
        float zz0, zz1;
        unpack2(fadd2(za, zb), zz0, zz1);

        unsigned u0 = __float_as_uint(b0), u1 = __float_as_uint(b1);
        float2 xo = make_float2((float)(u0 & 15u), (float)(u1 & 15u));
        float m0 = __uint_as_float(u0 & 0xFFFFFFF0u);
        float m1 = __uint_as_float(u1 & 0xFFFFFFF0u);
        float2 dm = make_float2(sqrtf(fmaxf(zz0 + m0, 0.0f)),
                                sqrtf(fmaxf(zz1 + m1, 0.0f)));

        __stcs((float2*)(out + 2 * p), xo);
        __stcs((float2*)(out + (size_t)NPIX + 2 * p), dm);
    }
}

extern "C" void kernel_launch(void* const* d_in, const int* in_sizes, int n_in,
                              void* d_out, int out_size) {
    const float* z = (const float*)d_in[0];  // (15, 2048, 2048) fp32
    const float* v = (const float*)d_in[1];  // (16, 15) fp32
    float* out = (float*)d_out;              // [X (as float) | dmin], each NPIX

    void* wp = nullptr;
    cudaGetSymbolAddress(&wp, c_wp);         // global alias of constant bank
    prep_kernel<<<1, 32>>>(v, (ulonglong2*)wp);

    cudaFuncSetAttribute(gum_kernel, cudaFuncAttributeMaxDynamicSharedMemorySize,
                         SMEM_BYTES);
    gum_kernel<<<NBLK, TPB, SMEM_BYTES>>>(z, out);
}

// round 16
// speedup vs baseline: 1.2880x; 1.1918x over previous
#include <cuda_runtime.h>

#define KV 16
#define DIM 15
#define NPIX (2048 * 2048)
#define TPB 256
// one thread = 4 pixels, as two packed f32x2 pairs per plane (LDG.128)

typedef unsigned long long u64;

__device__ __forceinline__ u64 ffma2(u64 a, u64 b, u64 c) {
    u64 d;
    asm("fma.rn.f32x2 %0, %1, %2, %3;" : "=l"(d) : "l"(a), "l"(b), "l"(c));
    return d;
}
__device__ __forceinline__ u64 fadd2(u64 a, u64 b) {
    u64 d;
    asm("add.rn.f32x2 %0, %1, %2;" : "=l"(d) : "l"(a), "l"(b));
    return d;
}
__device__ __forceinline__ u64 pack2(float x, float y) {
    u64 p;
    asm("mov.b64 %0, {%1, %2};" : "=l"(p) : "f"(x), "f"(y));
    return p;
}
__device__ __forceinline__ void unpack2(u64 p, float& x, float& y) {
    asm("mov.b64 {%0, %1}, %2;" : "=f"(x), "=f"(y) : "l"(p));
}

// Embed vertex index k into the low 4 mantissa bits of t (one LOP3), so the
// argmin collapses to a chain of FMNMX. Perturbation <= 16 ulp.
__device__ __forceinline__ float embed_idx(float t, int k) {
    unsigned r;
    asm("lop3.b32 %0, %1, 0xFFFFFFF0, %2, 0xEA;"  // (a & b) | c
        : "=r"(r) : "r"(__float_as_uint(t)), "r"(k));
    return __uint_as_float(r);
}

// Weight layout, per vertex k: 8 ulonglong2.
//   [k][m].x / .y = packed (-2*v[k][2m], dup) / (-2*v[k][2m+1], dup)  for m<7
//   [k][7].x      = packed pair for j=14
//   [k][7].y      = packed (||v_k||^2, ||v_k||^2)
__constant__ ulonglong2 c_wp[KV][8];

// prep writes through the global alias of c_wp; const cache refills per launch.
__global__ void prep_kernel(const float* __restrict__ v, ulonglong2* __restrict__ wp) {
    const int t = threadIdx.x;
    if (t < KV) {
        float b = 0.0f;
        #pragma unroll
        for (int j = 0; j < DIM; ++j) {
            float a = v[t * DIM + j];
            b = fmaf(a, a, b);
        }
        #pragma unroll
        for (int m = 0; m < 7; ++m) {
            float w0 = -2.0f * v[t * DIM + 2 * m];
            float w1 = -2.0f * v[t * DIM + 2 * m + 1];
            wp[t * 8 + m] = make_ulonglong2(pack2(w0, w0), pack2(w1, w1));
        }
        float w14 = -2.0f * v[t * DIM + 14];
        wp[t * 8 + 7] = make_ulonglong2(pack2(w14, w14), pack2(b, b));
    }
}

// t_k = ||v_k||^2 - 2 v_k . z   (monotone in distance; argmin matches)
// dmin = sqrt(max(zz + t_min, 0))

__global__ __launch_bounds__(TPB, 3) void gum_kernel(const float* __restrict__ z,
                                                     float* __restrict__ out) {
    const int t = threadIdx.x;
    const size_t p = (size_t)blockIdx.x * TPB + t;  // pixel-quad index
    const u64* zp = (const u64*)z;

    // Front-batch all 15 global loads as LDG.128 (1920 B in flight per warp)
    u64 zlo[DIM], zhi[DIM];
    #pragma unroll
    for (int j = 0; j < DIM; ++j) {
        ulonglong2 zv = __ldcs((const ulonglong2*)(zp + (size_t)j * (NPIX / 2) + 2 * p));
        zlo[j] = zv.x;  // pixels (4p, 4p+1)
        zhi[j] = zv.y;  // pixels (4p+2, 4p+3)
    }

    float b0 = __int_as_float(0x7f7fffff), b1 = b0, b2 = b0, b3 = b0;  // FLT_MAX

    #pragma unroll
    for (int k = 0; k < KV; ++k) {
        // Single accumulator chain per pixel-pair: the fully-unrolled k-loop
        // already provides 32 independent chains of ILP.
        ulonglong2 w7 = c_wp[k][7];
        u64 la = w7.y, ha = w7.y;         // ||v_k||^2 pair
        #pragma unroll
        for (int m = 0; m < 7; ++m) {
            ulonglong2 w = c_wp[k][m];
            la = ffma2(w.x, zlo[2 * m], la);
            ha = ffma2(w.x, zhi[2 * m], ha);
            la = ffma2(w.y, zlo[2 * m + 1], la);
            ha = ffma2(w.y, zhi[2 * m + 1], ha);
        }
        la = ffma2(w7.x, zlo[14], la);    // last-issued load folded last
        ha = ffma2(w7.x, zhi[14], ha);

        float t0, t1, t2, t3;
        unpack2(la, t0, t1);
        unpack2(ha, t2, t3);
        // branchless argmin: LOP3 (embed k) + FMNMX per pixel
        b0 = fminf(b0, embed_idx(t0, k));
        b1 = fminf(b1, embed_idx(t1, k));
        b2 = fminf(b2, embed_idx(t2, k));
        b3 = fminf(b3, embed_idx(t3, k));
    }

    // ||z||^2 (zlo/zhi stay live through the k-loop anyway)
    u64 zza_lo = 0ull, zzb_lo = 0ull, zza_hi = 0ull, zzb_hi = 0ull;
    #pragma unroll
    for (int j = 0; j < DIM; j += 2) {
        zza_lo = ffma2(zlo[j], zlo[j], zza_lo);
        zza_hi = ffma2(zhi[j], zhi[j], zza_hi);
        if (j + 1 < DIM) {
            zzb_lo = ffma2(zlo[j + 1], zlo[j + 1], zzb_lo);
            zzb_hi = ffma2(zhi[j + 1], zhi[j + 1], zzb_hi);
        }
    }
    float zz0, zz1, zz2, zz3;
    unpack2(fadd2(zza_lo, zzb_lo), zz0, zz1);
    unpack2(fadd2(zza_hi, zzb_hi), zz2, zz3);

    // winner index = low 4 bits; masked value = t_min (16 ulp perturbation)
    unsigned u0 = __float_as_uint(b0), u1 = __float_as_uint(b1);
    unsigned u2 = __float_as_uint(b2), u3 = __float_as_uint(b3);
    float4 xo = make_float4((float)(u0 & 15u), (float)(u1 & 15u),
                            (float)(u2 & 15u), (float)(u3 & 15u));
    float m0 = __uint_as_float(u0 & 0xFFFFFFF0u);
    float m1 = __uint_as_float(u1 & 0xFFFFFFF0u);
    float m2 = __uint_as_float(u2 & 0xFFFFFFF0u);
    float m3 = __uint_as_float(u3 & 0xFFFFFFF0u);
    float4 dm = make_float4(sqrtf(fmaxf(zz0 + m0, 0.0f)),
                            sqrtf(fmaxf(zz1 + m1, 0.0f)),
                            sqrtf(fmaxf(zz2 + m2, 0.0f)),
                            sqrtf(fmaxf(zz3 + m3, 0.0f)));

    __stcs((float4*)(out + 4 * p), xo);
    __stcs((float4*)(out + (size_t)NPIX + 4 * p), dm);
}

extern "C" void kernel_launch(void* const* d_in, const int* in_sizes, int n_in,
                              void* d_out, int out_size) {
    const float* z = (const float*)d_in[0];  // (15, 2048, 2048) fp32
    const float* v = (const float*)d_in[1];  // (16, 15) fp32
    float* out = (float*)d_out;              // [X (as float) | dmin], each NPIX

    void* wp = nullptr;
    cudaGetSymbolAddress(&wp, c_wp);         // global alias of constant bank
    prep_kernel<<<1, 32>>>(v, (ulonglong2*)wp);

    const int nblocks = NPIX / (TPB * 4);    // 4096
    gum_kernel<<<nblocks, TPB>>>(z, out);
}

// round 17
// speedup vs baseline: 1.3090x; 1.0163x over previous
#include <cuda_runtime.h>

#define KV 16
#define DIM 15
#define NPIX (2048 * 2048)
#define TPB 256
// one thread = 4 pixels, as two packed f32x2 pairs per plane (LDG.128)

typedef unsigned long long u64;

__device__ __forceinline__ u64 ffma2(u64 a, u64 b, u64 c) {
    u64 d;
    asm("fma.rn.f32x2 %0, %1, %2, %3;" : "=l"(d) : "l"(a), "l"(b), "l"(c));
    return d;
}
__device__ __forceinline__ u64 fadd2(u64 a, u64 b) {
    u64 d;
    asm("add.rn.f32x2 %0, %1, %2;" : "=l"(d) : "l"(a), "l"(b));
    return d;
}
__device__ __forceinline__ u64 pack2(float x, float y) {
    u64 p;
    asm("mov.b64 %0, {%1, %2};" : "=l"(p) : "f"(x), "f"(y));
    return p;
}
__device__ __forceinline__ void unpack2(u64 p, float& x, float& y) {
    asm("mov.b64 {%0, %1}, %2;" : "=f"(x), "=f"(y) : "l"(p));
}

// Embed vertex index k into the low 4 mantissa bits of t (one LOP3), so the
// argmin collapses to a chain of FMNMX. Perturbation <= 16 ulp.
__device__ __forceinline__ float embed_idx(float t, int k) {
    unsigned r;
    asm("lop3.b32 %0, %1, 0xFFFFFFF0, %2, 0xEA;"  // (a & b) | c
        : "=r"(r) : "r"(__float_as_uint(t)), "r"(k));
    return __uint_as_float(r);
}

// Weight layout, per vertex k: 8 ulonglong2.
//   [k][m].x / .y = packed (-2*v[k][2m], dup) / (-2*v[k][2m+1], dup)  for m<7
//   [k][7].x      = packed pair for j=14
//   [k][7].y      = packed (||v_k||^2, ||v_k||^2)
__constant__ ulonglong2 c_wp[KV][8];

// prep writes through the global alias of c_wp; const cache refills per launch.
// Triggers programmatic launch completion as soon as the stores are issued so
// the PDL-launched gum_kernel can start its grid at the earliest legal point.
__global__ void prep_kernel(const float* __restrict__ v, ulonglong2* __restrict__ wp) {
    const int t = threadIdx.x;
    if (t < KV) {
        float b = 0.0f;
        #pragma unroll
        for (int j = 0; j < DIM; ++j) {
            float a = v[t * DIM + j];
            b = fmaf(a, a, b);
        }
        #pragma unroll
        for (int m = 0; m < 7; ++m) {
            float w0 = -2.0f * v[t * DIM + 2 * m];
            float w1 = -2.0f * v[t * DIM + 2 * m + 1];
            wp[t * 8 + m] = make_ulonglong2(pack2(w0, w0), pack2(w1, w1));
        }
        float w14 = -2.0f * v[t * DIM + 14];
        wp[t * 8 + 7] = make_ulonglong2(pack2(w14, w14), pack2(b, b));
    }
    cudaTriggerProgrammaticLaunchCompletion();
}

// t_k = ||v_k||^2 - 2 v_k . z   (monotone in distance; argmin matches)
// dmin = sqrt(max(zz + t_min, 0))

__global__ __launch_bounds__(TPB, 3) void gum_kernel(const float* __restrict__ z,
                                                     float* __restrict__ out) {
    const int t = threadIdx.x;
    const size_t p = (size_t)blockIdx.x * TPB + t;  // pixel-quad index
    const u64* zp = (const u64*)z;

    // Front-batch all 15 global loads as LDG.128 (1920 B in flight per warp).
    // These do NOT depend on prep_kernel, so under PDL they overlap its tail.
    u64 zlo[DIM], zhi[DIM];
    #pragma unroll
    for (int j = 0; j < DIM; ++j) {
        ulonglong2 zv = __ldcs((const ulonglong2*)(zp + (size_t)j * (NPIX / 2) + 2 * p));
        zlo[j] = zv.x;  // pixels (4p, 4p+1)
        zhi[j] = zv.y;  // pixels (4p+2, 4p+3)
    }

    // PDL: wait until prep_kernel's constant writes are visible before the
    // first c_wp access (const cache fills after this point).
    cudaGridDependencySynchronize();

    float b0 = __int_as_float(0x7f7fffff), b1 = b0, b2 = b0, b3 = b0;  // FLT_MAX

    #pragma unroll
    for (int k = 0; k < KV; ++k) {
        // Single accumulator chain per pixel-pair: the fully-unrolled k-loop
        // already provides 32 independent chains of ILP.
        ulonglong2 w7 = c_wp[k][7];
        u64 la = w7.y, ha = w7.y;         // ||v_k||^2 pair
        #pragma unroll
        for (int m = 0; m < 7; ++m) {
            ulonglong2 w = c_wp[k][m];
            la = ffma2(w.x, zlo[2 * m], la);
            ha = ffma2(w.x, zhi[2 * m], ha);
            la = ffma2(w.y, zlo[2 * m + 1], la);
            ha = ffma2(w.y, zhi[2 * m + 1], ha);
        }
        la = ffma2(w7.x, zlo[14], la);    // last-issued load folded last
        ha = ffma2(w7.x, zhi[14], ha);

        float t0, t1, t2, t3;
        unpack2(la, t0, t1);
        unpack2(ha, t2, t3);
        // branchless argmin: LOP3 (embed k) + FMNMX per pixel
        b0 = fminf(b0, embed_idx(t0, k));
        b1 = fminf(b1, embed_idx(t1, k));
        b2 = fminf(b2, embed_idx(t2, k));
        b3 = fminf(b3, embed_idx(t3, k));
    }

    // ||z||^2 (zlo/zhi stay live through the k-loop anyway)
    u64 zza_lo = 0ull, zzb_lo = 0ull, zza_hi = 0ull, zzb_hi = 0ull;
    #pragma unroll
    for (int j = 0; j < DIM; j += 2) {
        zza_lo = ffma2(zlo[j], zlo[j], zza_lo);
        zza_hi = ffma2(zhi[j], zhi[j], zza_hi);
        if (j + 1 < DIM) {
            zzb_lo = ffma2(zlo[j + 1], zlo[j + 1], zzb_lo);
            zzb_hi = ffma2(zhi[j + 1], zhi[j + 1], zzb_hi);
        }
    }
    float zz0, zz1, zz2, zz3;
    unpack2(fadd2(zza_lo, zzb_lo), zz0, zz1);
    unpack2(fadd2(zza_hi, zzb_hi), zz2, zz3);

    // winner index = low 4 bits; masked value = t_min (16 ulp perturbation)
    unsigned u0 = __float_as_uint(b0), u1 = __float_as_uint(b1);
    unsigned u2 = __float_as_uint(b2), u3 = __float_as_uint(b3);
    float4 xo = make_float4((float)(u0 & 15u), (float)(u1 & 15u),
                            (float)(u2 & 15u), (float)(u3 & 15u));
    float m0 = __uint_as_float(u0 & 0xFFFFFFF0u);
    float m1 = __uint_as_float(u1 & 0xFFFFFFF0u);
    float m2 = __uint_as_float(u2 & 0xFFFFFFF0u);
    float m3 = __uint_as_float(u3 & 0xFFFFFFF0u);
    float4 dm = make_float4(sqrtf(fmaxf(zz0 + m0, 0.0f)),
                            sqrtf(fmaxf(zz1 + m1, 0.0f)),
                            sqrtf(fmaxf(zz2 + m2, 0.0f)),
                            sqrtf(fmaxf(zz3 + m3, 0.0f)));

    __stcs((float4*)(out + 4 * p), xo);
    __stcs((float4*)(out + (size_t)NPIX + 4 * p), dm);
}

extern "C" void kernel_launch(void* const* d_in, const int* in_sizes, int n_in,
                              void* d_out, int out_size) {
    const float* z = (const float*)d_in[0];  // (15, 2048, 2048) fp32
    const float* v = (const float*)d_in[1];  // (16, 15) fp32
    float* out = (float*)d_out;              // [X (as float) | dmin], each NPIX

    void* wp = nullptr;
    cudaGetSymbolAddress(&wp, c_wp);         // global alias of constant bank
    prep_kernel<<<1, 32>>>(v, (ulonglong2*)wp);

    // Launch gum_kernel with programmatic dependent launch so it overlaps
    // prep's launch/drain latency; the in-kernel gridDependencySynchronize
    // enforces the data dependency.
    cudaLaunchConfig_t cfg = {};
    cfg.gridDim = dim3(NPIX / (TPB * 4), 1, 1);   // 4096
    cfg.blockDim = dim3(TPB, 1, 1);
    cudaLaunchAttribute attr[1];
    attr[0].id = cudaLaunchAttributeProgrammaticStreamSerialization;
    attr[0].val.programmaticStreamSerializationAllowed = 1;
    cfg.attrs = attr;
    cfg.numAttrs = 1;
    cudaLaunchKernelEx(&cfg, gum_kernel, z, out);
}